// round 3
// baseline (speedup 1.0000x reference)
#include <cuda_runtime.h>

typedef unsigned long long u64;

#define NBATCH 512
#define NTT    257
#define NIVL   256
#define NIN    32
#define NH     128
#define NBN    256
#define NOUT   64
#define GRID_CTAS 128
#define TPB    512

// ---- shared memory layout (float offsets) ----
#define OFF_W3  0        // [256][128] k-major
#define OFF_W1  32768    // u64 wpairs [4 cg][128 k]  = 1024 floats
#define OFF_W2  33792    // u64 wpairs [4 cg][256 k]  = 2048 floats
#define OFF_B3  35840    // [128]
#define OFF_B1  35968    // [8]
#define OFF_B2  35976    // [8]
#define OFF_MW  35984    // [128][2]
#define OFF_SW  36240    // [128][2]
#define OFF_MB  36496    // [2]
#define OFF_SB  36498    // [2]
#define OFF_DX  36500    // [128][32]
#define OFF_ACT 40596    // 2 x [16][128] double-buffered act chunks
#define OFF_KP  44692    // [128][17] stage-3 partials
#define SMEM_FLOATS 46868
#define SMEM_BYTES  (SMEM_FLOATS * 4)

// ---- global scratch ----
__device__ float g_zc[NBATCH * NH];
__device__ float g_h1[NBATCH * NBN];
__device__ float g_h2[NBATCH * NBN];

struct PadU { unsigned v; unsigned pad[31]; };
__device__ PadU g_cnt[4];
__device__ PadU g_rel[4];

// ---- f32x2 helpers ----
__device__ __forceinline__ u64 pack2(float x, float y) {
    u64 r;
    asm("mov.b64 %0, {%1, %2};" : "=l"(r) : "f"(x), "f"(y));
    return r;
}
__device__ __forceinline__ float2 unpack2(u64 v) {
    float2 r;
    asm("mov.b64 {%0, %1}, %2;" : "=f"(r.x), "=f"(r.y) : "l"(v));
    return r;
}
__device__ __forceinline__ void fma2(u64& d, u64 a, u64 b) {
    asm("fma.rn.f32x2 %0, %1, %2, %0;" : "+l"(d) : "l"(a), "l"(b));
}

// tanh(x) = 1 - 2/(exp(2x)+1) via ex2/rcp approx (~1e-6 abs err)
__device__ __forceinline__ float fast_tanh(float x) {
    float e;
    asm("ex2.approx.f32 %0, %1;" : "=f"(e) : "f"(x * 2.8853900817779268f));
    float r;
    asm("rcp.approx.f32 %0, %1;" : "=f"(r) : "f"(e + 1.0f));
    return fmaf(-2.0f, r, 1.0f);
}

__device__ __forceinline__ float softplus_f(float x) {
    return fmaxf(x, 0.0f) + log1pf(expf(-fabsf(x)));
}

// ---- 32-CTA group barrier (monotonic phase) ----
__device__ __forceinline__ void gbar(int grp, unsigned ph) {
    __syncthreads();
    if (threadIdx.x == 0) {
        __threadfence();
        unsigned old = atomicAdd(&g_cnt[grp].v, 1u);
        if (old == 31u) {
            g_cnt[grp].v = 0u;
            asm volatile("st.release.gpu.u32 [%0], %1;"
                         :: "l"(&g_rel[grp].v), "r"(ph) : "memory");
        } else {
            unsigned v;
            do {
                asm volatile("ld.acquire.gpu.u32 %0, [%1];"
                             : "=r"(v) : "l"(&g_rel[grp].v) : "memory");
            } while (v != ph);
        }
    }
    __syncthreads();
}

__device__ __forceinline__ void gbar_reset(int grp) {
    __syncthreads();
    if (threadIdx.x == 0) {
        __threadfence();
        unsigned old = atomicAdd(&g_cnt[grp].v, 1u);
        if (old == 31u) {
            g_cnt[grp].v = 0u;
            asm volatile("st.release.gpu.u32 [%0], %1;"
                         :: "l"(&g_rel[grp].v), "r"(0u) : "memory");
        } else {
            unsigned v;
            do {
                asm volatile("ld.acquire.gpu.u32 %0, [%1];"
                             : "=r"(v) : "l"(&g_rel[grp].v) : "memory");
            } while (v != 0u);
        }
    }
}

// stash 4 floats of an activation chunk into k-major smem buffer
__device__ __forceinline__ void stash4(float* buf, int row, int q, float4 p) {
    buf[(q * 4 + 0) * 128 + row] = p.x;
    buf[(q * 4 + 1) * 128 + row] = p.y;
    buf[(q * 4 + 2) * 128 + row] = p.z;
    buf[(q * 4 + 3) * 128 + row] = p.w;
}

// ---- MLP stage: out[128 rows, 8 cols] = relu(in[128,KT] @ Wslice + b) ----
// 512 threads: r = tid&127 (row), cg = tid>>7 (col pair cg*2, cg*2+1).
// sWp: u64 wpair array [cg][KT], pre-packed at init.
template <int KT>
__device__ __forceinline__ void mlp_stage(const float* __restrict__ gin,
                                          const u64* __restrict__ sWp,
                                          const float* __restrict__ sb,
                                          float* __restrict__ goutBase,
                                          float* __restrict__ sAct, int tid) {
    const int r  = tid & 127;
    const int cg = tid >> 7;           // 0..3
    u64 acc = pack2(sb[cg * 2], sb[cg * 2 + 1]);

    const int row = tid >> 2, q = tid & 3;
    const float* gsrc = gin + (size_t)row * KT;
    float4 p = __ldcg((const float4*)gsrc + q);

    const u64* wbase = sWp + (size_t)cg * KT;
    const int NCH = KT / 16;
#pragma unroll 1
    for (int kc = 0; kc < NCH; kc++) {
        float* buf = sAct + (kc & 1) * 2048;
        stash4(buf, row, q, p);
        __syncthreads();
        if (kc + 1 < NCH)
            p = __ldcg((const float4*)(gsrc + (kc + 1) * 16) + q);
        const u64* wk = wbase + kc * 16;
#pragma unroll
        for (int k2 = 0; k2 < 8; k2++) {
            ulonglong2 wp = *(const ulonglong2*)(wk + k2 * 2);
            float a0 = buf[(k2 * 2 + 0) * 128 + r];
            float a1 = buf[(k2 * 2 + 1) * 128 + r];
            fma2(acc, pack2(a0, a0), wp.x);
            fma2(acc, pack2(a1, a1), wp.y);
        }
    }
    float2 u = unpack2(acc);
    float2 o;
    o.x = fmaxf(u.x, 0.f);
    o.y = fmaxf(u.y, 0.f);
    __stcg((float2*)(goutBase + (size_t)r * NBN + cg * 2), o);
}

// ---- stage 3: k[128 rows, 4 h] = einsum(tanh(h2@W3slice + b3), dxdt) ----
// 512 threads, 4x8 tile: tx = tid&15 (8 cols), ty = tid>>4 (4 rows).
__device__ __forceinline__ void stage3(const float* __restrict__ gin,
                                       const float* __restrict__ sW3,
                                       const float* __restrict__ sb3,
                                       const float* __restrict__ sDx,
                                       float* __restrict__ sAct,
                                       float* __restrict__ sKp,
                                       int tid, float& kout) {
    const int tx = tid & 15, ty = tid >> 5 == 0 ? (tid >> 4) : (tid >> 4); // ty = tid>>4
    const int tyv = tid >> 4;          // 0..31
    u64 acc[4][4];
#pragma unroll
    for (int j = 0; j < 4; j++)
#pragma unroll
        for (int pcol = 0; pcol < 4; pcol++) acc[j][pcol] = 0ull;
    (void)tx; (void)ty;

    const int row = tid >> 2, q = tid & 3;
    const float* gsrc = gin + (size_t)row * NBN;
    float4 p = __ldcg((const float4*)gsrc + q);

#pragma unroll 1
    for (int kc = 0; kc < 16; kc++) {
        float* buf = sAct + (kc & 1) * 2048;
        stash4(buf, row, q, p);
        __syncthreads();
        if (kc < 15)
            p = __ldcg((const float4*)(gsrc + (kc + 1) * 16) + q);
#pragma unroll
        for (int k = 0; k < 16; k++) {
            float4 av = *(const float4*)(buf + k * 128 + (tyv << 2));
            const float* wr = sW3 + ((kc << 4) + k) * 128 + (tx << 3);
            u64 w0 = *(const u64*)(wr + 0);
            u64 w1 = *(const u64*)(wr + 2);
            u64 w2 = *(const u64*)(wr + 4);
            u64 w3 = *(const u64*)(wr + 6);
            float aj[4] = {av.x, av.y, av.z, av.w};
#pragma unroll
            for (int j = 0; j < 4; j++) {
                u64 aa = pack2(aj[j], aj[j]);
                fma2(acc[j][0], aa, w0);
                fma2(acc[j][1], aa, w1);
                fma2(acc[j][2], aa, w2);
                fma2(acc[j][3], aa, w3);
            }
        }
    }

    // epilogue: bias + tanh + contract with dxdt over this thread's 8 i's
    const int hloc = tx >> 2;
    const int qq   = tx & 3;
    const int i0   = qq * 8;
#pragma unroll
    for (int j = 0; j < 4; j++) {
        float s = 0.f;
        const float* dx = sDx + (tyv * 4 + j) * 32 + i0;
#pragma unroll
        for (int pcol = 0; pcol < 4; pcol++) {
            float2 u = unpack2(acc[j][pcol]);
            int c = (tx << 3) + pcol * 2;
            float y0 = fast_tanh(u.x + sb3[c]);
            float y1 = fast_tanh(u.y + sb3[c + 1]);
            s = fmaf(y0, dx[pcol * 2], s);
            s = fmaf(y1, dx[pcol * 2 + 1], s);
        }
        sKp[(tyv * 4 + j) * 17 + hloc * 4 + qq] = s;
    }
    __syncthreads();

    // owner reduce: thread (r = tid&127, hh = tid>>7) owns h = g*4+hh
    const int r  = tid & 127;
    const int hh = tid >> 7;
    const float* kp = sKp + r * 17 + hh * 4;
    kout = (kp[0] + kp[1]) + (kp[2] + kp[3]);
}

// ================= persistent kernel =================
__global__ void __launch_bounds__(TPB, 1)
cde_persistent(const float* __restrict__ t, const float* __restrict__ z0,
               const float* __restrict__ X,
               const float* __restrict__ W1, const float* __restrict__ b1,
               const float* __restrict__ W2, const float* __restrict__ b2,
               const float* __restrict__ W3, const float* __restrict__ b3,
               const float* __restrict__ mW, const float* __restrict__ mb,
               const float* __restrict__ sWp, const float* __restrict__ sbp,
               float* __restrict__ out) {
    extern __shared__ float sm[];
    float* sW3  = sm + OFF_W3;
    u64*   sW1p = (u64*)(sm + OFF_W1);
    u64*   sW2p = (u64*)(sm + OFF_W2);
    float* sb3  = sm + OFF_B3;
    float* sb1  = sm + OFF_B1;
    float* sb2  = sm + OFF_B2;
    float* smW  = sm + OFF_MW;
    float* ssW  = sm + OFF_SW;
    float* smb  = sm + OFF_MB;
    float* ssb  = sm + OFF_SB;
    float* sDx  = sm + OFF_DX;
    float* sAct = sm + OFF_ACT;
    float* sKp  = sm + OFF_KP;

    const int tid = threadIdx.x;
    const int bb  = blockIdx.x >> 5;   // batch-block group 0..3
    const int g   = blockIdx.x & 31;   // group-local id 0..31
    const int rowBase = bb * 128;

    // ---- stage weights into smem ----
    for (int i = tid; i < 256 * 32; i += TPB) {            // W3 slice [256][128]
        int k = i >> 5, c4 = i & 31;
        float4 v = __ldg((const float4*)(W3 + (size_t)k * 4096 + g * 128) + c4);
        *(float4*)(sW3 + k * 128 + c4 * 4) = v;
    }
    for (int i = tid; i < 4 * 128; i += TPB) {             // W1 wpairs [4][128]
        int cg = i >> 7, k = i & 127;
        float w0 = __ldg(&W1[(size_t)k * 256 + g * 8 + cg * 2]);
        float w1 = __ldg(&W1[(size_t)k * 256 + g * 8 + cg * 2 + 1]);
        sW1p[cg * 128 + k] = pack2(w0, w1);
    }
    for (int i = tid; i < 4 * 256; i += TPB) {             // W2 wpairs [4][256]
        int cg = i >> 8, k = i & 255;
        float w0 = __ldg(&W2[(size_t)k * 256 + g * 8 + cg * 2]);
        float w1 = __ldg(&W2[(size_t)k * 256 + g * 8 + cg * 2 + 1]);
        sW2p[cg * 256 + k] = pack2(w0, w1);
    }
    for (int i = tid; i < 128; i += TPB) sb3[i] = __ldg(&b3[g * 128 + i]);
    if (tid < 8)  sb1[tid] = __ldg(&b1[g * 8 + tid]);
    if (tid >= 8 && tid < 16) sb2[tid - 8] = __ldg(&b2[g * 8 + tid - 8]);
    for (int i = tid; i < 256; i += TPB) {                 // mW/sW slices [128][2]
        int h = i >> 1, c = i & 1;
        smW[i] = __ldg(&mW[(size_t)h * 64 + g * 2 + c]);
        ssW[i] = __ldg(&sWp[(size_t)h * 64 + g * 2 + c]);
    }
    if (tid < 2)  smb[tid] = __ldg(&mb[g * 2 + tid]);
    if (tid >= 2 && tid < 4) ssb[tid - 2] = __ldg(&sbp[g * 2 + tid - 2]);
    __syncthreads();

    // ---- init owned z state: thread (r, hh) owns z[rowBase+r, g*4+hh] ----
    const int r  = tid & 127;
    const int hh = tid >> 7;               // 0..3
    const int h0 = g * 4 + hh;
    const int b  = rowBase + r;
    float zb = __ldg(&z0[(size_t)b * 128 + h0]);
    __stcg(g_zc + (size_t)b * 128 + h0, zb);

    unsigned phase = 0;
    gbar(bb, ++phase);

#pragma unroll 1
    for (int tau = 0; tau < NIVL; tau++) {
        float t0v = __ldg(&t[tau]);
        float t1v = __ldg(&t[tau + 1]);
        float dti = t1v - t0v;
        float hstep = dti * 0.25f;
        __syncthreads();
        for (int i = tid; i < 1024; i += TPB) {
            int rr = i >> 3, q = i & 7;
            const float* Xr = X + ((size_t)(rowBase + rr) * NTT + tau) * NIN;
            float4 x0 = __ldg((const float4*)Xr + q);
            float4 x1 = __ldg((const float4*)(Xr + NIN) + q);
            float4 d;
            d.x = (x1.x - x0.x) / dti;
            d.y = (x1.y - x0.y) / dti;
            d.z = (x1.z - x0.z) / dti;
            d.w = (x1.w - x0.w) / dti;
            *(float4*)(sDx + rr * 32 + (q << 2)) = d;
        }
        __syncthreads();

#pragma unroll 1
        for (int sub = 0; sub < 4; sub++) {
            float a_acc = 0.f, kp = 0.f;
#pragma unroll 1
            for (int s = 0; s < 4; s++) {
                float cs = (s == 0) ? 0.f : ((s == 3) ? 1.f : 0.5f);
                float zc = fmaf(cs * hstep, kp, zb);
                __stcg(g_zc + (size_t)b * 128 + h0, zc);
                gbar(bb, ++phase);

                mlp_stage<128>(g_zc + (size_t)rowBase * 128, sW1p, sb1,
                               g_h1 + (size_t)rowBase * 256 + g * 8, sAct, tid);
                gbar(bb, ++phase);

                mlp_stage<256>(g_h1 + (size_t)rowBase * 256, sW2p, sb2,
                               g_h2 + (size_t)rowBase * 256 + g * 8, sAct, tid);
                gbar(bb, ++phase);

                float kv;
                stage3(g_h2 + (size_t)rowBase * 256, sW3, sb3, sDx, sAct, sKp,
                       tid, kv);
                float ws = (s == 0 || s == 3) ? 1.f : 2.f;
                a_acc = fmaf(ws, kv, a_acc);
                kp = kv;
            }
            zb = fmaf(hstep / 6.0f, a_acc, zb);
        }

        // ---- interval end: publish z, then output heads ----
        __stcg(g_zc + (size_t)b * 128 + h0, zb);
        gbar(bb, ++phase);
        {
            // thread (r, hh): hh 0/1 -> mean cols g*2+hh, hh 2/3 -> std cols
            const float* wsel = (hh >= 2) ? ssW : smW;
            const int col = hh & 1;
            float acc = (hh >= 2) ? ssb[col] : smb[col];
            const float* zrow = g_zc + (size_t)b * 128;
#pragma unroll 4
            for (int h = 0; h < 128; h++) {
                float zv = __ldcg(zrow + h);
                acc = fmaf(zv, wsel[h * 2 + col], acc);
            }
            if (hh >= 2) acc = softplus_f(acc);
            float* dst = out + ((hh >= 2) ? (size_t)NBATCH * NIVL * NOUT : 0)
                         + ((size_t)b * NIVL + tau) * NOUT + g * 2 + col;
            *dst = acc;
        }
    }

    gbar_reset(bb);
}

extern "C" void kernel_launch(void* const* d_in, const int* in_sizes, int n_in,
                              void* d_out, int out_size) {
    const float* t   = (const float*)d_in[0];
    const float* z0  = (const float*)d_in[1];
    const float* X   = (const float*)d_in[2];
    const float* W1  = (const float*)d_in[3];
    const float* b1  = (const float*)d_in[4];
    const float* W2  = (const float*)d_in[5];
    const float* b2  = (const float*)d_in[6];
    const float* W3  = (const float*)d_in[7];
    const float* b3  = (const float*)d_in[8];
    const float* mW  = (const float*)d_in[9];
    const float* mb  = (const float*)d_in[10];
    const float* sW  = (const float*)d_in[11];
    const float* sb  = (const float*)d_in[12];
    float* out = (float*)d_out;

    cudaFuncSetAttribute(cde_persistent,
                         cudaFuncAttributeMaxDynamicSharedMemorySize, SMEM_BYTES);
    cde_persistent<<<GRID_CTAS, TPB, SMEM_BYTES>>>(t, z0, X, W1, b1, W2, b2,
                                                   W3, b3, mW, mb, sW, sb, out);
}

// round 4
// speedup vs baseline: 1.3290x; 1.3290x over previous
#include <cuda_runtime.h>

typedef unsigned long long u64;

#define NBATCH 512
#define NTT    257
#define NIVL   256
#define NIN    32
#define NH     128
#define NBN    256
#define NOUT   64
#define GRID_CTAS 128
#define TPB    256

// ---- shared memory layout (float offsets) ----
#define OFF_W3  0        // [256][128] k-major
#define OFF_W1  32768    // [128][8]
#define OFF_W2  33792    // [256][8]
#define OFF_B3  35840    // [128]
#define OFF_B1  35968    // [8]
#define OFF_B2  35976    // [8]
#define OFF_MW  35984    // [128][2]
#define OFF_SW  36240    // [128][2]
#define OFF_MB  36496    // [2]
#define OFF_SB  36498    // [2] (+pad)
#define OFF_DX  36504    // [128][32]
#define OFF_ACT 40600    // 2 x 4096 floats (double-buffered chunks)
#define OFF_KP  48792    // [128][17]
#define SMEM_FLOATS 50968
#define SMEM_BYTES  (SMEM_FLOATS * 4)

// ---- global scratch: parity(2) double-buffered, COLUMN-major per bb-block ----
// zc: [2][4 bb][128 h][128 r], h1/h2: [2][4 bb][256 c][128 r]
__device__ float g_zc[2][4 * NH * 128];
__device__ float g_h1[2][4 * NBN * 128];
__device__ float g_h2[2][4 * NBN * 128];

// dataflow flags: one per (group, producer CTA)
__device__ unsigned g_fz[4][32];
__device__ unsigned g_f1[4][32];
__device__ unsigned g_f2[4][32];

struct PadU { unsigned v; unsigned pad[31]; };
__device__ PadU g_cnt[4];
__device__ PadU g_rel[4];

// ---- f32x2 helpers ----
__device__ __forceinline__ u64 pack2(float x, float y) {
    u64 r;
    asm("mov.b64 %0, {%1, %2};" : "=l"(r) : "f"(x), "f"(y));
    return r;
}
__device__ __forceinline__ float2 unpack2(u64 v) {
    float2 r;
    asm("mov.b64 {%0, %1}, %2;" : "=f"(r.x), "=f"(r.y) : "l"(v));
    return r;
}
__device__ __forceinline__ void fma2(u64& d, u64 a, u64 b) {
    asm("fma.rn.f32x2 %0, %1, %2, %0;" : "+l"(d) : "l"(a), "l"(b));
}

__device__ __forceinline__ float fast_tanh(float x) {
    float e;
    asm("ex2.approx.f32 %0, %1;" : "=f"(e) : "f"(x * 2.8853900817779268f));
    float r;
    asm("rcp.approx.f32 %0, %1;" : "=f"(r) : "f"(e + 1.0f));
    return fmaf(-2.0f, r, 1.0f);
}

__device__ __forceinline__ float softplus_f(float x) {
    return fmaxf(x, 0.0f) + log1pf(expf(-fabsf(x)));
}

// ---- producer publish / consumer wait (dataflow sync) ----
__device__ __forceinline__ void publish(unsigned* f, int g, unsigned ph) {
    __syncthreads();                 // all threads' stcg done
    if (threadIdx.x == 0) {
        __threadfence();             // order data stores before flag
        asm volatile("st.release.gpu.u32 [%0], %1;"
                     :: "l"(f + g), "r"(ph) : "memory");
    }
}
__device__ __forceinline__ void wait_flags(unsigned* f, unsigned ph) {
    if (threadIdx.x < 32) {
        const unsigned* a = f + threadIdx.x;
        unsigned v;
        do {
            asm volatile("ld.acquire.gpu.u32 %0, [%1];"
                         : "=r"(v) : "l"(a) : "memory");
        } while ((int)(v - ph) < 0);
    }
    __syncthreads();
}

// ---- legacy group barrier (end-of-kernel reset only) ----
__device__ __forceinline__ void gbar_val(int grp, unsigned target) {
    __syncthreads();
    if (threadIdx.x == 0) {
        __threadfence();
        unsigned old = atomicAdd(&g_cnt[grp].v, 1u);
        if (old == 31u) {
            g_cnt[grp].v = 0u;
            asm volatile("st.release.gpu.u32 [%0], %1;"
                         :: "l"(&g_rel[grp].v), "r"(target) : "memory");
        } else {
            unsigned v;
            do {
                asm volatile("ld.acquire.gpu.u32 %0, [%1];"
                             : "=r"(v) : "l"(&g_rel[grp].v) : "memory");
            } while (v != target);
        }
    }
    __syncthreads();
}

// ---- MLP stage: gout_cm[8 cols][128 r] = relu(gin_cm[KT][128] ^T-contract) ----
// gin_cm is column(k)-major: [KT][128 rows]. 256 threads.
template <int KT>
__device__ __forceinline__ void mlp_stage(const float* __restrict__ gin_cm,
                                          const float* __restrict__ sW,
                                          const float* __restrict__ sb,
                                          float* __restrict__ gout_cm,
                                          float* __restrict__ sAct, int tid) {
    const int r  = tid & 127;
    const int ch = tid >> 7;           // 0/1 -> cols ch*4..+4
    u64 acc0 = pack2(sb[ch * 4 + 0], sb[ch * 4 + 1]);
    u64 acc1 = pack2(sb[ch * 4 + 2], sb[ch * 4 + 3]);

    const float4* src = (const float4*)gin_cm;
    float4 v0 = __ldcg(src + 0 * 256 + tid);
    float4 v1 = __ldcg(src + 1 * 256 + tid);
    float4 v2 = __ldcg(src + 2 * 256 + tid);
    float4 v3 = __ldcg(src + 3 * 256 + tid);

    const int NCH = KT / 32;
#pragma unroll 1
    for (int kc = 0; kc < NCH; kc++) {
        float4* buf4 = (float4*)(sAct + (kc & 1) * 4096);
        buf4[0 * 256 + tid] = v0;
        buf4[1 * 256 + tid] = v1;
        buf4[2 * 256 + tid] = v2;
        buf4[3 * 256 + tid] = v3;
        __syncthreads();
        if (kc + 1 < NCH) {
            const float4* sn = src + (kc + 1) * 1024;
            v0 = __ldcg(sn + 0 * 256 + tid);
            v1 = __ldcg(sn + 1 * 256 + tid);
            v2 = __ldcg(sn + 2 * 256 + tid);
            v3 = __ldcg(sn + 3 * 256 + tid);
        }
        const float* buf = sAct + (kc & 1) * 4096;
        const float* wk  = sW + kc * 32 * 8 + ch * 4;
#pragma unroll
        for (int k = 0; k < 32; k++) {
            float a = buf[k * 128 + r];
            u64 aa  = pack2(a, a);
            ulonglong2 w = *(const ulonglong2*)(wk + k * 8);
            fma2(acc0, aa, w.x);
            fma2(acc1, aa, w.y);
        }
        __syncthreads();
    }
    float2 u0 = unpack2(acc0), u1 = unpack2(acc1);
    __stcg(gout_cm + (ch * 4 + 0) * 128 + r, fmaxf(u0.x, 0.f));
    __stcg(gout_cm + (ch * 4 + 1) * 128 + r, fmaxf(u0.y, 0.f));
    __stcg(gout_cm + (ch * 4 + 2) * 128 + r, fmaxf(u1.x, 0.f));
    __stcg(gout_cm + (ch * 4 + 3) * 128 + r, fmaxf(u1.y, 0.f));
}

// ---- stage 3: k[128 rows, 2 h] = einsum(tanh(h2@W3slice + b3), dxdt) ----
// 8x8 per-thread tile: ty = tid>>4 (row block), tx = tid&15 (col block).
__device__ __forceinline__ void stage3(const float* __restrict__ gin_cm,
                                       const float* __restrict__ sW3,
                                       const float* __restrict__ sb3,
                                       const float* __restrict__ sDx,
                                       float* __restrict__ sAct,
                                       float* __restrict__ sKp,
                                       int tid, float& k0, float& k1) {
    const int ty = tid >> 4, tx = tid & 15;
    u64 acc[8][4];
#pragma unroll
    for (int j = 0; j < 8; j++)
#pragma unroll
        for (int p = 0; p < 4; p++) acc[j][p] = 0ull;

    const float4* src = (const float4*)gin_cm;
    float4 v0 = __ldcg(src + tid);
    float4 v1 = __ldcg(src + 256 + tid);

#pragma unroll 1
    for (int kc = 0; kc < 16; kc++) {
        float4* buf4 = (float4*)(sAct + (kc & 1) * 2048);
        buf4[tid] = v0;
        buf4[256 + tid] = v1;
        __syncthreads();
        if (kc < 15) {
            const float4* sn = src + (kc + 1) * 512;
            v0 = __ldcg(sn + tid);
            v1 = __ldcg(sn + 256 + tid);
        }
        const float* buf = sAct + (kc & 1) * 2048;
#pragma unroll
        for (int k = 0; k < 16; k++) {
            const float* ar = buf + k * 128 + (ty << 3);
            float4 a0 = *(const float4*)ar;
            float4 a1 = *(const float4*)(ar + 4);
            const float* wr = sW3 + ((kc << 4) + k) * 128 + (tx << 3);
            ulonglong2 wa = *(const ulonglong2*)wr;
            ulonglong2 wb = *(const ulonglong2*)(wr + 4);
            float av[8] = {a0.x, a0.y, a0.z, a0.w, a1.x, a1.y, a1.z, a1.w};
#pragma unroll
            for (int j = 0; j < 8; j++) {
                u64 aa = pack2(av[j], av[j]);
                fma2(acc[j][0], aa, wa.x);
                fma2(acc[j][1], aa, wa.y);
                fma2(acc[j][2], aa, wb.x);
                fma2(acc[j][3], aa, wb.y);
            }
        }
        __syncthreads();
    }

    // epilogue: bias + tanh + contract with dxdt over this thread's 8 i's
    const int hloc = tx >> 2;          // 0..3 (local h)
    const int qq   = tx & 3;           // i-block
    const int i0   = qq * 8;
    float part[8];
#pragma unroll
    for (int j = 0; j < 8; j++) {
        float s = 0.f;
        const float* dx = sDx + (ty * 8 + j) * 32 + i0;
#pragma unroll
        for (int p = 0; p < 4; p++) {
            float2 u = unpack2(acc[j][p]);
            int c = (tx << 3) + p * 2;
            float y0 = fast_tanh(u.x + sb3[c]);
            float y1 = fast_tanh(u.y + sb3[c + 1]);
            s = fmaf(y0, dx[p * 2], s);
            s = fmaf(y1, dx[p * 2 + 1], s);
        }
        part[j] = s;
    }
#pragma unroll
    for (int j = 0; j < 8; j++)
        sKp[(ty * 8 + j) * 17 + hloc * 4 + qq] = part[j];
    __syncthreads();

    // owner reduce: thread (r = tid&127, hh = tid>>7) owns h = g*4 + hh*2 + {0,1}
    const int r  = tid & 127;
    const int hh = tid >> 7;
    const float* kp = sKp + r * 17;
    const int c0 = (hh * 2) * 4;
    const int c1 = (hh * 2 + 1) * 4;
    k0 = (kp[c0] + kp[c0 + 1]) + (kp[c0 + 2] + kp[c0 + 3]);
    k1 = (kp[c1] + kp[c1 + 1]) + (kp[c1 + 2] + kp[c1 + 3]);
}

// ================= persistent kernel =================
__global__ void __launch_bounds__(TPB, 1)
cde_persistent(const float* __restrict__ t, const float* __restrict__ z0,
               const float* __restrict__ X,
               const float* __restrict__ W1, const float* __restrict__ b1,
               const float* __restrict__ W2, const float* __restrict__ b2,
               const float* __restrict__ W3, const float* __restrict__ b3,
               const float* __restrict__ mW, const float* __restrict__ mb,
               const float* __restrict__ sWp, const float* __restrict__ sbp,
               float* __restrict__ out) {
    extern __shared__ float sm[];
    float* sW3  = sm + OFF_W3;
    float* sW1  = sm + OFF_W1;
    float* sW2  = sm + OFF_W2;
    float* sb3  = sm + OFF_B3;
    float* sb1  = sm + OFF_B1;
    float* sb2  = sm + OFF_B2;
    float* smW  = sm + OFF_MW;
    float* ssW  = sm + OFF_SW;
    float* smb  = sm + OFF_MB;
    float* ssb  = sm + OFF_SB;
    float* sDx  = sm + OFF_DX;
    float* sAct = sm + OFF_ACT;
    float* sKp  = sm + OFF_KP;

    const int tid = threadIdx.x;
    const int bb  = blockIdx.x >> 5;   // batch-block 0..3
    const int g   = blockIdx.x & 31;   // column group 0..31
    const int rowBase = bb * 128;

    // ---- stage weights into smem ----
    for (int i = tid; i < 256 * 32; i += TPB) {            // W3 slice [256][128]
        int k = i >> 5, c4 = i & 31;
        float4 v = __ldg((const float4*)(W3 + (size_t)k * 4096 + g * 128) + c4);
        *(float4*)(sW3 + k * 128 + c4 * 4) = v;
    }
    for (int i = tid; i < 128 * 2; i += TPB) {             // W1 slice [128][8]
        int k = i >> 1, c4 = i & 1;
        *(float4*)(sW1 + k * 8 + c4 * 4) =
            __ldg((const float4*)(W1 + (size_t)k * 256 + g * 8) + c4);
    }
    for (int i = tid; i < 256 * 2; i += TPB) {             // W2 slice [256][8]
        int k = i >> 1, c4 = i & 1;
        *(float4*)(sW2 + k * 8 + c4 * 4) =
            __ldg((const float4*)(W2 + (size_t)k * 256 + g * 8) + c4);
    }
    for (int i = tid; i < 128; i += TPB) sb3[i] = __ldg(&b3[g * 128 + i]);
    if (tid < 8)  sb1[tid] = __ldg(&b1[g * 8 + tid]);
    if (tid >= 8 && tid < 16) sb2[tid - 8] = __ldg(&b2[g * 8 + tid - 8]);
    for (int i = tid; i < 256; i += TPB) {                 // mW/sW slices [128][2]
        int h = i >> 1, c = i & 1;
        smW[i] = __ldg(&mW[(size_t)h * 64 + g * 2 + c]);
        ssW[i] = __ldg(&sWp[(size_t)h * 64 + g * 2 + c]);
    }
    if (tid < 2)  smb[tid] = __ldg(&mb[g * 2 + tid]);
    if (tid >= 2 && tid < 4) ssb[tid - 2] = __ldg(&sbp[g * 2 + tid - 2]);
    __syncthreads();

    // ---- owned z state: thread (r, hh) owns z[rowBase+r, g*4+hh*2 .. +2] ----
    const int r  = tid & 127;
    const int hh = tid >> 7;               // 0/1
    const int h0 = g * 4 + hh * 2;
    const int b  = rowBase + r;
    float zb0 = __ldg(&z0[(size_t)b * 128 + h0]);
    float zb1 = __ldg(&z0[(size_t)b * 128 + h0 + 1]);

    // per-bb column-major bases
    const size_t zOff  = (size_t)bb * (NH * 128);
    const size_t hOff  = (size_t)bb * (NBN * 128);

    unsigned ph = 0;

#pragma unroll 1
    for (int tau = 0; tau < NIVL; tau++) {
        float t0v = __ldg(&t[tau]);
        float t1v = __ldg(&t[tau + 1]);
        float dti = t1v - t0v;
        float hstep = dti * 0.25f;
        __syncthreads();
        for (int i = tid; i < 1024; i += TPB) {
            int rr = i >> 3, q = i & 7;
            const float* Xr = X + ((size_t)(rowBase + rr) * NTT + tau) * NIN;
            float4 x0 = __ldg((const float4*)Xr + q);
            float4 x1 = __ldg((const float4*)(Xr + NIN) + q);
            float4 d;
            d.x = (x1.x - x0.x) / dti;
            d.y = (x1.y - x0.y) / dti;
            d.z = (x1.z - x0.z) / dti;
            d.w = (x1.w - x0.w) / dti;
            *(float4*)(sDx + rr * 32 + (q << 2)) = d;
        }
        __syncthreads();

#pragma unroll 1
        for (int sub = 0; sub < 4; sub++) {
            float a0 = 0.f, a1 = 0.f, kp0 = 0.f, kp1 = 0.f;
#pragma unroll 1
            for (int s = 0; s < 4; s++) {
                float cs = (s == 0) ? 0.f : ((s == 3) ? 1.f : 0.5f);
                float zc0 = fmaf(cs * hstep, kp0, zb0);
                float zc1 = fmaf(cs * hstep, kp1, zb1);

                // publish zc (column-major)
                ++ph; int pz = ph & 1;
                __stcg(&g_zc[pz][zOff + (size_t)h0 * 128 + r], zc0);
                __stcg(&g_zc[pz][zOff + (size_t)(h0 + 1) * 128 + r], zc1);
                publish(g_fz[bb], g, ph);
                wait_flags(g_fz[bb], ph);

                // stage 1
                ++ph; int p1 = ph & 1;
                mlp_stage<128>(&g_zc[pz][zOff], sW1, sb1,
                               &g_h1[p1][hOff + (size_t)(g * 8) * 128], sAct, tid);
                publish(g_f1[bb], g, ph);
                wait_flags(g_f1[bb], ph);

                // stage 2
                ++ph; int p2 = ph & 1;
                mlp_stage<256>(&g_h1[p1][hOff], sW2, sb2,
                               &g_h2[p2][hOff + (size_t)(g * 8) * 128], sAct, tid);
                publish(g_f2[bb], g, ph);
                wait_flags(g_f2[bb], ph);

                // stage 3 (local result)
                float k0, k1;
                stage3(&g_h2[p2][hOff], sW3, sb3, sDx, sAct, sKp, tid, k0, k1);
                float ws = (s == 0 || s == 3) ? 1.f : 2.f;
                a0 = fmaf(ws, k0, a0);
                a1 = fmaf(ws, k1, a1);
                kp0 = k0; kp1 = k1;
            }
            float h6 = hstep / 6.0f;
            zb0 = fmaf(h6, a0, zb0);
            zb1 = fmaf(h6, a1, zb1);
        }

        // ---- interval end: publish final z, then output heads ----
        ++ph; int pz = ph & 1;
        __stcg(&g_zc[pz][zOff + (size_t)h0 * 128 + r], zb0);
        __stcg(&g_zc[pz][zOff + (size_t)(h0 + 1) * 128 + r], zb1);
        publish(g_fz[bb], g, ph);
        wait_flags(g_fz[bb], ph);
        {
            const float* wsel = hh ? ssW : smW;
            float acc0 = hh ? ssb[0] : smb[0];
            float acc1 = hh ? ssb[1] : smb[1];
            const float* zbase = &g_zc[pz][zOff];
#pragma unroll 8
            for (int h = 0; h < 128; h++) {
                float zv = __ldcg(zbase + (size_t)h * 128 + r);
                acc0 = fmaf(zv, wsel[h * 2 + 0], acc0);
                acc1 = fmaf(zv, wsel[h * 2 + 1], acc1);
            }
            if (hh) { acc0 = softplus_f(acc0); acc1 = softplus_f(acc1); }
            float* dst = out + (hh ? (size_t)NBATCH * NIVL * NOUT : 0)
                         + ((size_t)b * NIVL + tau) * NOUT + g * 2;
            dst[0] = acc0;
            dst[1] = acc1;
        }
    }

    // ---- end-of-kernel reset for deterministic graph replay ----
    gbar_val(bb, 1u);                  // all CTAs of group done with flag reads
    if (tid == 0) {
        g_fz[bb][g] = 0u;
        g_f1[bb][g] = 0u;
        g_f2[bb][g] = 0u;
    }
    gbar_val(bb, 0u);                  // restores g_rel to 0 (g_cnt self-resets)
}

extern "C" void kernel_launch(void* const* d_in, const int* in_sizes, int n_in,
                              void* d_out, int out_size) {
    const float* t   = (const float*)d_in[0];
    const float* z0  = (const float*)d_in[1];
    const float* X   = (const float*)d_in[2];
    const float* W1  = (const float*)d_in[3];
    const float* b1  = (const float*)d_in[4];
    const float* W2  = (const float*)d_in[5];
    const float* b2  = (const float*)d_in[6];
    const float* W3  = (const float*)d_in[7];
    const float* b3  = (const float*)d_in[8];
    const float* mW  = (const float*)d_in[9];
    const float* mb  = (const float*)d_in[10];
    const float* sW  = (const float*)d_in[11];
    const float* sb  = (const float*)d_in[12];
    float* out = (float*)d_out;

    cudaFuncSetAttribute(cde_persistent,
                         cudaFuncAttributeMaxDynamicSharedMemorySize, SMEM_BYTES);
    cde_persistent<<<GRID_CTAS, TPB, SMEM_BYTES>>>(t, z0, X, W1, b1, W2, b2,
                                                   W3, b3, mW, mb, sW, sb, out);
}

// round 6
// speedup vs baseline: 1.7612x; 1.3252x over previous
#include <cuda_runtime.h>
#include <cuda_bf16.h>

typedef unsigned long long u64;
typedef unsigned int u32;

#define NBATCH 512
#define NTT    257
#define NIVL   256
#define NIN    32
#define NH     128
#define NBN    256
#define NOUT   64
#define GRID_CTAS 128
#define TPB    256

// ---- shared memory byte offsets ----
#define SM_FRAGB 0          // [16 kt][16 nt][32 lane] uint4 (bhi0,bhi1,blo0,blo1) = 128KB
#define SM_W1    131072     // [128][8] f32
#define SM_W2    135168     // [256][8] f32
#define SM_B3    143360     // [128] f32
#define SM_B1    143872     // [8]
#define SM_B2    143904     // [8]
#define SM_MW    143936     // [128][2]
#define SM_SW    144960     // [128][2]
#define SM_MB    145984     // [2]
#define SM_SB    145992     // [2] (+pad)
#define SM_DX    146016     // [128][33] f32
#define SM_ACT   162912     // 2 x 4096 f32 stage-1/2 staging
#define SM_KB    195680     // [128][17] f32
#define SMEM_BYTES 204384

// ---- global scratch ----
__device__ float g_zc[2][4 * NH * 128];    // col-major [h][r] per bb
__device__ float g_h1[2][4 * NBN * 128];   // col-major [c][r] per bb
// h2 exchanged as mma A-fragments: [parity][bb][ (kt*8+mt)*32+lane ] uint4 (a0..a3)
__device__ uint4 g_fAhi[2][4][4096];
__device__ uint4 g_fAlo[2][4][4096];

__device__ unsigned g_fz[4][32];
__device__ unsigned g_f1[4][32];
__device__ unsigned g_f2[4][32];

struct PadU { unsigned v; unsigned pad[31]; };
__device__ PadU g_cnt[4];
__device__ PadU g_rel[4];

// ---- f32x2 helpers (stage 1/2 SIMT GEMM) ----
__device__ __forceinline__ u64 pack2(float x, float y) {
    u64 r;
    asm("mov.b64 %0, {%1, %2};" : "=l"(r) : "f"(x), "f"(y));
    return r;
}
__device__ __forceinline__ float2 unpack2(u64 v) {
    float2 r;
    asm("mov.b64 {%0, %1}, %2;" : "=f"(r.x), "=f"(r.y) : "l"(v));
    return r;
}
__device__ __forceinline__ void fma2(u64& d, u64 a, u64 b) {
    asm("fma.rn.f32x2 %0, %1, %2, %0;" : "+l"(d) : "l"(a), "l"(b));
}

__device__ __forceinline__ float fast_tanh(float x) {
    float e;
    asm("ex2.approx.f32 %0, %1;" : "=f"(e) : "f"(x * 2.8853900817779268f));
    float r;
    asm("rcp.approx.f32 %0, %1;" : "=f"(r) : "f"(e + 1.0f));
    return fmaf(-2.0f, r, 1.0f);
}
__device__ __forceinline__ float softplus_f(float x) {
    return fmaxf(x, 0.0f) + log1pf(expf(-fabsf(x)));
}

// ---- mma.sync m16n8k16 row.col f32.bf16.bf16.f32 ----
__device__ __forceinline__ void mma16816(float* c, uint4 a, u32 b0, u32 b1) {
    asm volatile(
        "mma.sync.aligned.m16n8k16.row.col.f32.bf16.bf16.f32 "
        "{%0,%1,%2,%3}, {%4,%5,%6,%7}, {%8,%9}, {%0,%1,%2,%3};"
        : "+f"(c[0]), "+f"(c[1]), "+f"(c[2]), "+f"(c[3])
        : "r"(a.x), "r"(a.y), "r"(a.z), "r"(a.w), "r"(b0), "r"(b1));
}

// bf16 hi/lo split helpers
__device__ __forceinline__ void bf_split(float x, unsigned short& h, unsigned short& l) {
    __nv_bfloat16 bh = __float2bfloat16_rn(x);
    __nv_bfloat16 bl = __float2bfloat16_rn(x - __bfloat162float(bh));
    h = __bfloat16_as_ushort(bh);
    l = __bfloat16_as_ushort(bl);
}

// ---- dataflow publish / wait ----
__device__ __forceinline__ void publish(unsigned* f, int g, unsigned ph) {
    __syncthreads();
    if (threadIdx.x == 0) {
        __threadfence();
        asm volatile("st.release.gpu.u32 [%0], %1;" :: "l"(f + g), "r"(ph) : "memory");
    }
}
__device__ __forceinline__ void wait_flags(unsigned* f, unsigned ph) {
    if (threadIdx.x < 32) {
        const unsigned* a = f + threadIdx.x;
        unsigned v;
        do {
            asm volatile("ld.acquire.gpu.u32 %0, [%1];" : "=r"(v) : "l"(a) : "memory");
        } while ((int)(v - ph) < 0);
    }
    __syncthreads();
}
__device__ __forceinline__ void gbar_val(int grp, unsigned target) {
    __syncthreads();
    if (threadIdx.x == 0) {
        __threadfence();
        unsigned old = atomicAdd(&g_cnt[grp].v, 1u);
        if (old == 31u) {
            g_cnt[grp].v = 0u;
            asm volatile("st.release.gpu.u32 [%0], %1;"
                         :: "l"(&g_rel[grp].v), "r"(target) : "memory");
        } else {
            unsigned v;
            do {
                asm volatile("ld.acquire.gpu.u32 %0, [%1];"
                             : "=r"(v) : "l"(&g_rel[grp].v) : "memory");
            } while (v != target);
        }
    }
    __syncthreads();
}

// ---- stage 1: h1[8 cols col-major] = relu(z @ W1slice + b1) ----
__device__ __forceinline__ void stage1(const float* __restrict__ gin_cm,
                                       const float* __restrict__ sW,
                                       const float* __restrict__ sb,
                                       float* __restrict__ gout_cm,
                                       float* __restrict__ sAct, int tid) {
    const int r  = tid & 127;
    const int ch = tid >> 7;
    u64 acc0 = pack2(sb[ch * 4 + 0], sb[ch * 4 + 1]);
    u64 acc1 = pack2(sb[ch * 4 + 2], sb[ch * 4 + 3]);

    const float4* src = (const float4*)gin_cm;
    float4 v0 = __ldcg(src + 0 * 256 + tid);
    float4 v1 = __ldcg(src + 1 * 256 + tid);
    float4 v2 = __ldcg(src + 2 * 256 + tid);
    float4 v3 = __ldcg(src + 3 * 256 + tid);

#pragma unroll 1
    for (int kc = 0; kc < 4; kc++) {
        float4* buf4 = (float4*)(sAct + (kc & 1) * 4096);
        buf4[0 * 256 + tid] = v0;
        buf4[1 * 256 + tid] = v1;
        buf4[2 * 256 + tid] = v2;
        buf4[3 * 256 + tid] = v3;
        __syncthreads();
        if (kc + 1 < 4) {
            const float4* sn = src + (kc + 1) * 1024;
            v0 = __ldcg(sn + 0 * 256 + tid);
            v1 = __ldcg(sn + 1 * 256 + tid);
            v2 = __ldcg(sn + 2 * 256 + tid);
            v3 = __ldcg(sn + 3 * 256 + tid);
        }
        const float* buf = sAct + (kc & 1) * 4096;
        const float* wk  = sW + kc * 32 * 8 + ch * 4;
#pragma unroll
        for (int k = 0; k < 32; k++) {
            float a = buf[k * 128 + r];
            u64 aa  = pack2(a, a);
            ulonglong2 w = *(const ulonglong2*)(wk + k * 8);
            fma2(acc0, aa, w.x);
            fma2(acc1, aa, w.y);
        }
        __syncthreads();
    }
    float2 u0 = unpack2(acc0), u1 = unpack2(acc1);
    __stcg(gout_cm + (ch * 4 + 0) * 128 + r, fmaxf(u0.x, 0.f));
    __stcg(gout_cm + (ch * 4 + 1) * 128 + r, fmaxf(u0.y, 0.f));
    __stcg(gout_cm + (ch * 4 + 2) * 128 + r, fmaxf(u1.x, 0.f));
    __stcg(gout_cm + (ch * 4 + 3) * 128 + r, fmaxf(u1.y, 0.f));
}

// ---- stage 2: h2 cols -> bf16 hi/lo mma A-fragments in gmem ----
__device__ __forceinline__ void stage2_frag(const float* __restrict__ gin_cm,
                                            const float* __restrict__ sW,
                                            const float* __restrict__ sb,
                                            u32* __restrict__ fHi,
                                            u32* __restrict__ fLo,
                                            int g, float* __restrict__ sAct, int tid) {
    const int r  = tid & 127;
    const int ch = tid >> 7;
    u64 acc0 = pack2(sb[ch * 4 + 0], sb[ch * 4 + 1]);
    u64 acc1 = pack2(sb[ch * 4 + 2], sb[ch * 4 + 3]);

    const float4* src = (const float4*)gin_cm;
    float4 v0 = __ldcg(src + 0 * 256 + tid);
    float4 v1 = __ldcg(src + 1 * 256 + tid);
    float4 v2 = __ldcg(src + 2 * 256 + tid);
    float4 v3 = __ldcg(src + 3 * 256 + tid);

#pragma unroll 1
    for (int kc = 0; kc < 8; kc++) {
        float4* buf4 = (float4*)(sAct + (kc & 1) * 4096);
        buf4[0 * 256 + tid] = v0;
        buf4[1 * 256 + tid] = v1;
        buf4[2 * 256 + tid] = v2;
        buf4[3 * 256 + tid] = v3;
        __syncthreads();
        if (kc + 1 < 8) {
            const float4* sn = src + (kc + 1) * 1024;
            v0 = __ldcg(sn + 0 * 256 + tid);
            v1 = __ldcg(sn + 1 * 256 + tid);
            v2 = __ldcg(sn + 2 * 256 + tid);
            v3 = __ldcg(sn + 3 * 256 + tid);
        }
        const float* buf = sAct + (kc & 1) * 4096;
        const float* wk  = sW + kc * 32 * 8 + ch * 4;
#pragma unroll
        for (int k = 0; k < 32; k++) {
            float a = buf[k * 128 + r];
            u64 aa  = pack2(a, a);
            ulonglong2 w = *(const ulonglong2*)(wk + k * 8);
            fma2(acc0, aa, w.x);
            fma2(acc1, aa, w.y);
        }
        __syncthreads();
    }
    float2 u0 = unpack2(acc0), u1 = unpack2(acc1);
    float o0 = fmaxf(u0.x, 0.f), o1 = fmaxf(u0.y, 0.f);
    float o2 = fmaxf(u1.x, 0.f), o3 = fmaxf(u1.y, 0.f);

    unsigned short h0, h1, h2, h3, l0, l1, l2, l3;
    bf_split(o0, h0, l0); bf_split(o1, h1, l1);
    bf_split(o2, h2, l2); bf_split(o3, h3, l3);
    u32 hi01 = ((u32)h1 << 16) | h0;
    u32 hi23 = ((u32)h3 << 16) | h2;
    u32 lo01 = ((u32)l1 << 16) | l0;
    u32 lo23 = ((u32)l3 << 16) | l2;

    // fragment slot: cols c = g*8 + ch*4 + j ; kt = g>>1 ; within-tile k = 8*(g&1)+4ch+j
    const int kt   = g >> 1;
    const int mt   = r >> 4;
    const int lane = (r & 7) * 4 + 2 * ch;
    const int reg  = ((r >> 3) & 1) + 2 * (g & 1);
    const int idx0 = ((kt * 8 + mt) * 32 + lane) * 4 + reg;
    __stcg(&fHi[idx0], hi01);
    __stcg(&fHi[idx0 + 4], hi23);
    __stcg(&fLo[idx0], lo01);
    __stcg(&fLo[idx0 + 4], lo23);
}

// ================= persistent kernel =================
__global__ void __launch_bounds__(TPB, 1)
cde_persistent(const float* __restrict__ t, const float* __restrict__ z0,
               const float* __restrict__ X,
               const float* __restrict__ W1, const float* __restrict__ b1,
               const float* __restrict__ W2, const float* __restrict__ b2,
               const float* __restrict__ W3, const float* __restrict__ b3,
               const float* __restrict__ mW, const float* __restrict__ mb,
               const float* __restrict__ sWp, const float* __restrict__ sbp,
               float* __restrict__ out) {
    extern __shared__ char smb[];
    uint4* sFragB = (uint4*)(smb + SM_FRAGB);
    float* sW1  = (float*)(smb + SM_W1);
    float* sW2  = (float*)(smb + SM_W2);
    float* sb3  = (float*)(smb + SM_B3);
    float* sb1  = (float*)(smb + SM_B1);
    float* sb2  = (float*)(smb + SM_B2);
    float* smW  = (float*)(smb + SM_MW);
    float* ssW  = (float*)(smb + SM_SW);
    float* smb_ = (float*)(smb + SM_MB);
    float* ssb  = (float*)(smb + SM_SB);
    float* sDx  = (float*)(smb + SM_DX);
    float* sAct = (float*)(smb + SM_ACT);
    float* sKb  = (float*)(smb + SM_KB);

    const int tid  = threadIdx.x;
    const int wid  = tid >> 5;
    const int lane = tid & 31;
    const int bb   = blockIdx.x >> 5;
    const int g    = blockIdx.x & 31;
    const int rowBase = bb * 128;

    // ---- init: W3 slice -> B fragments (hi/lo) in smem ----
    for (int i = tid; i < 16 * 16 * 32; i += TPB) {
        int ln = i & 31, nt = (i >> 5) & 15, kt = i >> 9;
        int nl = nt * 8 + (ln >> 2);
        int k0 = kt * 16 + (ln & 3) * 2;
        const float* wp = W3 + (size_t)k0 * 4096 + g * 128 + nl;
        unsigned short h0, h1, h8, h9, l0, l1, l8, l9;
        bf_split(wp[0],          h0, l0);
        bf_split(wp[4096],       h1, l1);
        bf_split(wp[8 * 4096],   h8, l8);
        bf_split(wp[9 * 4096],   h9, l9);
        uint4 v;
        v.x = ((u32)h1 << 16) | h0;   // bhi0: k0, k0+1
        v.y = ((u32)h9 << 16) | h8;   // bhi1: k0+8, k0+9
        v.z = ((u32)l1 << 16) | l0;   // blo0
        v.w = ((u32)l9 << 16) | l8;   // blo1
        sFragB[i] = v;
    }
    for (int i = tid; i < 128 * 2; i += TPB) {
        int k = i >> 1, c4 = i & 1;
        *(float4*)(sW1 + k * 8 + c4 * 4) =
            __ldg((const float4*)(W1 + (size_t)k * 256 + g * 8) + c4);
    }
    for (int i = tid; i < 256 * 2; i += TPB) {
        int k = i >> 1, c4 = i & 1;
        *(float4*)(sW2 + k * 8 + c4 * 4) =
            __ldg((const float4*)(W2 + (size_t)k * 256 + g * 8) + c4);
    }
    for (int i = tid; i < 128; i += TPB) sb3[i] = __ldg(&b3[g * 128 + i]);
    if (tid < 8)  sb1[tid] = __ldg(&b1[g * 8 + tid]);
    if (tid >= 8 && tid < 16) sb2[tid - 8] = __ldg(&b2[g * 8 + tid - 8]);
    for (int i = tid; i < 256; i += TPB) {
        int h = i >> 1, c = i & 1;
        smW[i] = __ldg(&mW[(size_t)h * 64 + g * 2 + c]);
        ssW[i] = __ldg(&sWp[(size_t)h * 64 + g * 2 + c]);
    }
    if (tid < 2)  smb_[tid] = __ldg(&mb[g * 2 + tid]);
    if (tid >= 2 && tid < 4) ssb[tid - 2] = __ldg(&sbp[g * 2 + tid - 2]);
    __syncthreads();

    // ---- RK state: thread tid<128 owns z[rowBase+tid, g*4 .. +3] ----
    float zb[4];
    if (tid < 128) {
#pragma unroll
        for (int h = 0; h < 4; h++)
            zb[h] = __ldg(&z0[(size_t)(rowBase + tid) * 128 + g * 4 + h]);
    }

    const size_t zOff  = (size_t)bb * (NH * 128);
    const size_t h1Off = (size_t)bb * (NBN * 128);

    unsigned ph = 0;
    const int r0 = wid * 16 + (lane >> 2);   // stage-3 epilogue row (this lane, c0/c1)
    const int t4 = lane & 3;

#pragma unroll 1
    for (int tau = 0; tau < NIVL; tau++) {
        float t0v = __ldg(&t[tau]);
        float t1v = __ldg(&t[tau + 1]);
        float dti = t1v - t0v;
        float hstep = dti * 0.25f;
        __syncthreads();
        for (int i = tid; i < 1024; i += TPB) {
            int rr = i >> 3, q = i & 7;
            const float* Xr = X + ((size_t)(rowBase + rr) * NTT + tau) * NIN;
            float4 x0 = __ldg((const float4*)Xr + q);
            float4 x1 = __ldg((const float4*)(Xr + NIN) + q);
            float* d = sDx + rr * 33 + q * 4;
            d[0] = (x1.x - x0.x) / dti;
            d[1] = (x1.y - x0.y) / dti;
            d[2] = (x1.z - x0.z) / dti;
            d[3] = (x1.w - x0.w) / dti;
        }
        __syncthreads();

        // hoist this thread's dxdt values for the interval
        float dx0[8], dx1[8];
#pragma unroll
        for (int q = 0; q < 8; q++) {
            int i = (q >> 1) * 8 + t4 * 2 + (q & 1);
            dx0[q] = sDx[r0 * 33 + i];
            dx1[q] = sDx[(r0 + 8) * 33 + i];
        }

#pragma unroll 1
        for (int sub = 0; sub < 4; sub++) {
            float a_acc[4] = {0.f, 0.f, 0.f, 0.f};
            float kp[4]    = {0.f, 0.f, 0.f, 0.f};
#pragma unroll 1
            for (int s = 0; s < 4; s++) {
                float cs = (s == 0) ? 0.f : ((s == 3) ? 1.f : 0.5f);

                // publish zc (col-major)
                ++ph; int pz = ph & 1;
                if (tid < 128) {
#pragma unroll
                    for (int h = 0; h < 4; h++) {
                        float zc = fmaf(cs * hstep, kp[h], zb[h]);
                        __stcg(&g_zc[pz][zOff + (size_t)(g * 4 + h) * 128 + tid], zc);
                    }
                }
                publish(g_fz[bb], g, ph);
                wait_flags(g_fz[bb], ph);

                // stage 1
                ++ph; int p1 = ph & 1;
                stage1(&g_zc[pz][zOff], sW1, sb1,
                       &g_h1[p1][h1Off + (size_t)(g * 8) * 128], sAct, tid);
                publish(g_f1[bb], g, ph);
                wait_flags(g_f1[bb], ph);

                // stage 2 -> A fragments
                ++ph; int p2 = ph & 1;
                stage2_frag(&g_h1[p1][h1Off], sW2, sb2,
                            (u32*)&g_fAhi[p2][bb][0], (u32*)&g_fAlo[p2][bb][0],
                            g, sAct, tid);
                publish(g_f2[bb], g, ph);
                wait_flags(g_f2[bb], ph);

                // ---- stage 3: mma.sync over fragments ----
                float acc[16][4];
                {
                    const int c0b = t4 * 2;
#pragma unroll
                    for (int nt = 0; nt < 16; nt++) {
                        float bx = sb3[nt * 8 + c0b];
                        float by = sb3[nt * 8 + c0b + 1];
                        acc[nt][0] = bx; acc[nt][1] = by;
                        acc[nt][2] = bx; acc[nt][3] = by;
                    }
                }
                const uint4* fAh = &g_fAhi[p2][bb][0];
                const uint4* fAl = &g_fAlo[p2][bb][0];
                uint4 ah = __ldcg(fAh + (0 * 8 + wid) * 32 + lane);
                uint4 al = __ldcg(fAl + (0 * 8 + wid) * 32 + lane);
#pragma unroll 1
                for (int kt = 0; kt < 16; kt++) {
                    uint4 ahn, aln;
                    if (kt < 15) {
                        ahn = __ldcg(fAh + ((kt + 1) * 8 + wid) * 32 + lane);
                        aln = __ldcg(fAl + ((kt + 1) * 8 + wid) * 32 + lane);
                    }
                    const uint4* bfr = sFragB + (kt * 16) * 32 + lane;
#pragma unroll
                    for (int nt = 0; nt < 16; nt++) {
                        uint4 b = bfr[nt * 32];
                        mma16816(acc[nt], ah, b.x, b.y);   // Ahi*Bhi
                        mma16816(acc[nt], ah, b.z, b.w);   // Ahi*Blo
                        mma16816(acc[nt], al, b.x, b.y);   // Alo*Bhi
                    }
                    ah = ahn; al = aln;
                }

                // epilogue: tanh + dxdt contraction (bias pre-seeded)
                float kq0[4] = {0.f, 0.f, 0.f, 0.f};
                float kq1[4] = {0.f, 0.f, 0.f, 0.f};
#pragma unroll
                for (int nt = 0; nt < 16; nt++) {
                    int hl = nt >> 2, q = (nt & 3) * 2;
                    float y;
                    y = fast_tanh(acc[nt][0]); kq0[hl] = fmaf(y, dx0[q],     kq0[hl]);
                    y = fast_tanh(acc[nt][1]); kq0[hl] = fmaf(y, dx0[q + 1], kq0[hl]);
                    y = fast_tanh(acc[nt][2]); kq1[hl] = fmaf(y, dx1[q],     kq1[hl]);
                    y = fast_tanh(acc[nt][3]); kq1[hl] = fmaf(y, dx1[q + 1], kq1[hl]);
                }
#pragma unroll
                for (int hl = 0; hl < 4; hl++) {
                    sKb[r0 * 17 + hl * 4 + t4]       = kq0[hl];
                    sKb[(r0 + 8) * 17 + hl * 4 + t4] = kq1[hl];
                }
                __syncthreads();

                if (tid < 128) {
                    float ws = (s == 0 || s == 3) ? 1.f : 2.f;
                    const float* kb = sKb + tid * 17;
#pragma unroll
                    for (int h = 0; h < 4; h++) {
                        float kv = (kb[h * 4] + kb[h * 4 + 1])
                                 + (kb[h * 4 + 2] + kb[h * 4 + 3]);
                        a_acc[h] = fmaf(ws, kv, a_acc[h]);
                        kp[h] = kv;
                    }
                }
                __syncthreads();
            }
            if (tid < 128) {
                float h6 = hstep / 6.0f;
#pragma unroll
                for (int h = 0; h < 4; h++) zb[h] = fmaf(h6, a_acc[h], zb[h]);
            }
        }

        // ---- interval end: publish final z, output heads ----
        ++ph; int pz = ph & 1;
        if (tid < 128) {
#pragma unroll
            for (int h = 0; h < 4; h++)
                __stcg(&g_zc[pz][zOff + (size_t)(g * 4 + h) * 128 + tid], zb[h]);
        }
        publish(g_fz[bb], g, ph);
        wait_flags(g_fz[bb], ph);
        {
            const int r  = tid & 127;
            const int hh = tid >> 7;
            const int b  = rowBase + r;
            const float* wsel = hh ? ssW : smW;
            float acc0 = hh ? ssb[0] : smb_[0];
            float acc1 = hh ? ssb[1] : smb_[1];
            const float* zbase = &g_zc[pz][zOff];
#pragma unroll 8
            for (int h = 0; h < 128; h++) {
                float zv = __ldcg(zbase + (size_t)h * 128 + r);
                acc0 = fmaf(zv, wsel[h * 2 + 0], acc0);
                acc1 = fmaf(zv, wsel[h * 2 + 1], acc1);
            }
            if (hh) { acc0 = softplus_f(acc0); acc1 = softplus_f(acc1); }
            float* dst = out + (hh ? (size_t)NBATCH * NIVL * NOUT : 0)
                         + ((size_t)b * NIVL + tau) * NOUT + g * 2;
            dst[0] = acc0;
            dst[1] = acc1;
        }
    }

    // ---- end-of-kernel reset for deterministic graph replay ----
    gbar_val(bb, 1u);
    if (tid == 0) {
        g_fz[bb][g] = 0u;
        g_f1[bb][g] = 0u;
        g_f2[bb][g] = 0u;
    }
    gbar_val(bb, 0u);
}

extern "C" void kernel_launch(void* const* d_in, const int* in_sizes, int n_in,
                              void* d_out, int out_size) {
    const float* t   = (const float*)d_in[0];
    const float* z0  = (const float*)d_in[1];
    const float* X   = (const float*)d_in[2];
    const float* W1  = (const float*)d_in[3];
    const float* b1  = (const float*)d_in[4];
    const float* W2  = (const float*)d_in[5];
    const float* b2  = (const float*)d_in[6];
    const float* W3  = (const float*)d_in[7];
    const float* b3  = (const float*)d_in[8];
    const float* mW  = (const float*)d_in[9];
    const float* mb  = (const float*)d_in[10];
    const float* sW  = (const float*)d_in[11];
    const float* sb  = (const float*)d_in[12];
    float* out = (float*)d_out;

    cudaFuncSetAttribute(cde_persistent,
                         cudaFuncAttributeMaxDynamicSharedMemorySize, SMEM_BYTES);
    cde_persistent<<<GRID_CTAS, TPB, SMEM_BYTES>>>(t, z0, X, W1, b1, W2, b2,
                                                   W3, b3, mW, mb, sW, sb, out);
}

// round 7
// speedup vs baseline: 3.0332x; 1.7222x over previous
#include <cuda_runtime.h>
#include <cuda_bf16.h>

typedef unsigned long long u64;
typedef unsigned int u32;

#define NBATCH 512
#define NTT    257
#define NIVL   256
#define NIN    32
#define NH     128
#define NBN    256
#define NOUT   64
#define GRID_CTAS 128
#define TPB    256

// ---- shared memory byte offsets ----
#define SM_FRAGB 0          // [16 kt][16 nt][32 lane] uint4 (bhi0,bhi1,blo0,blo1) = 128KB
#define SM_W1    131072     // [128][8] f32
#define SM_W2    135168     // [256][8] f32
#define SM_B3    143360     // [128] f32
#define SM_B1    143872     // [8]
#define SM_B2    143904     // [8]
#define SM_MW    143936     // [128][2]
#define SM_SW    144960     // [128][2]
#define SM_MB    145984     // [2]
#define SM_SB    145992     // [2] (+pad)
#define SM_DX    146016     // [128][33] f32
#define SM_ACT   162912     // 2 x 4096 f32 stage-1/2 staging
#define SM_KB    195680     // [128][17] f32
#define SMEM_BYTES 204384

// ---- global scratch ----
__device__ float g_zc[2][4 * NH * 128];    // col-major [h][r] per bb
__device__ float g_h1[2][4 * NBN * 128];   // col-major [c][r] per bb
// h2 exchanged as mma A-fragments: [parity][bb][ (kt*8+mt)*32+lane ] uint4 (a0..a3)
__device__ uint4 g_fAhi[2][4][4096];
__device__ uint4 g_fAlo[2][4][4096];

// ---- arrive counters: one padded line per (group, stage-type) ----
struct PadCnt { unsigned v; unsigned pad[127]; };   // 512B stride: distinct L2 slices
__device__ PadCnt g_cz[4];
__device__ PadCnt g_c1[4];
__device__ PadCnt g_c2[4];

struct PadU { unsigned v; unsigned pad[31]; };
__device__ PadU g_cnt[4];
__device__ PadU g_rel[4];

// ---- f32x2 helpers (stage 1/2 SIMT GEMM) ----
__device__ __forceinline__ u64 pack2(float x, float y) {
    u64 r;
    asm("mov.b64 %0, {%1, %2};" : "=l"(r) : "f"(x), "f"(y));
    return r;
}
__device__ __forceinline__ float2 unpack2(u64 v) {
    float2 r;
    asm("mov.b64 {%0, %1}, %2;" : "=f"(r.x), "=f"(r.y) : "l"(v));
    return r;
}
__device__ __forceinline__ void fma2(u64& d, u64 a, u64 b) {
    asm("fma.rn.f32x2 %0, %1, %2, %0;" : "+l"(d) : "l"(a), "l"(b));
}

__device__ __forceinline__ float fast_tanh(float x) {
    float e;
    asm("ex2.approx.f32 %0, %1;" : "=f"(e) : "f"(x * 2.8853900817779268f));
    float r;
    asm("rcp.approx.f32 %0, %1;" : "=f"(r) : "f"(e + 1.0f));
    return fmaf(-2.0f, r, 1.0f);
}
__device__ __forceinline__ float softplus_f(float x) {
    return fmaxf(x, 0.0f) + log1pf(expf(-fabsf(x)));
}

// ---- mma.sync m16n8k16 row.col f32.bf16.bf16.f32 ----
__device__ __forceinline__ void mma16816(float* c, uint4 a, u32 b0, u32 b1) {
    asm volatile(
        "mma.sync.aligned.m16n8k16.row.col.f32.bf16.bf16.f32 "
        "{%0,%1,%2,%3}, {%4,%5,%6,%7}, {%8,%9}, {%0,%1,%2,%3};"
        : "+f"(c[0]), "+f"(c[1]), "+f"(c[2]), "+f"(c[3])
        : "r"(a.x), "r"(a.y), "r"(a.z), "r"(a.w), "r"(b0), "r"(b1));
}

// bf16 hi/lo split helpers
__device__ __forceinline__ void bf_split(float x, unsigned short& h, unsigned short& l) {
    __nv_bfloat16 bh = __float2bfloat16_rn(x);
    __nv_bfloat16 bl = __float2bfloat16_rn(x - __bfloat162float(bh));
    h = __bfloat16_as_ushort(bh);
    l = __bfloat16_as_ushort(bl);
}

// ---- counter publish / wait (contention-free dataflow sync) ----
// publish: CTA barrier orders all threads' prior stores before tid0's
// release-atomic (gpu-scope release fence composes through the CTA barrier).
__device__ __forceinline__ void publish_cnt(PadCnt* c) {
    __syncthreads();
    if (threadIdx.x == 0) {
        asm volatile("red.release.gpu.global.add.u32 [%0], %1;"
                     :: "l"(&c->v), "r"(1u) : "memory");
    }
}
// wait: single lane polls the counter; acquire pairs with producers' release.
__device__ __forceinline__ void wait_cnt(PadCnt* c, unsigned target) {
    if (threadIdx.x == 0) {
        unsigned v;
        do {
            asm volatile("ld.acquire.gpu.u32 %0, [%1];"
                         : "=r"(v) : "l"(&c->v) : "memory");
        } while ((int)(v - target) < 0);
    }
    __syncthreads();
}

// ---- legacy group barrier (end-of-kernel reset only) ----
__device__ __forceinline__ void gbar_val(int grp, unsigned target) {
    __syncthreads();
    if (threadIdx.x == 0) {
        __threadfence();
        unsigned old = atomicAdd(&g_cnt[grp].v, 1u);
        if (old == 31u) {
            g_cnt[grp].v = 0u;
            asm volatile("st.release.gpu.u32 [%0], %1;"
                         :: "l"(&g_rel[grp].v), "r"(target) : "memory");
        } else {
            unsigned v;
            do {
                asm volatile("ld.acquire.gpu.u32 %0, [%1];"
                             : "=r"(v) : "l"(&g_rel[grp].v) : "memory");
            } while (v != target);
        }
    }
    __syncthreads();
}

// ---- stage 1: h1[8 cols col-major] = relu(z @ W1slice + b1) ----
__device__ __forceinline__ void stage1(const float* __restrict__ gin_cm,
                                       const float* __restrict__ sW,
                                       const float* __restrict__ sb,
                                       float* __restrict__ gout_cm,
                                       float* __restrict__ sAct, int tid) {
    const int r  = tid & 127;
    const int ch = tid >> 7;
    u64 acc0 = pack2(sb[ch * 4 + 0], sb[ch * 4 + 1]);
    u64 acc1 = pack2(sb[ch * 4 + 2], sb[ch * 4 + 3]);

    const float4* src = (const float4*)gin_cm;
    float4 v0 = __ldcg(src + 0 * 256 + tid);
    float4 v1 = __ldcg(src + 1 * 256 + tid);
    float4 v2 = __ldcg(src + 2 * 256 + tid);
    float4 v3 = __ldcg(src + 3 * 256 + tid);

#pragma unroll 1
    for (int kc = 0; kc < 4; kc++) {
        float4* buf4 = (float4*)(sAct + (kc & 1) * 4096);
        buf4[0 * 256 + tid] = v0;
        buf4[1 * 256 + tid] = v1;
        buf4[2 * 256 + tid] = v2;
        buf4[3 * 256 + tid] = v3;
        __syncthreads();
        if (kc + 1 < 4) {
            const float4* sn = src + (kc + 1) * 1024;
            v0 = __ldcg(sn + 0 * 256 + tid);
            v1 = __ldcg(sn + 1 * 256 + tid);
            v2 = __ldcg(sn + 2 * 256 + tid);
            v3 = __ldcg(sn + 3 * 256 + tid);
        }
        const float* buf = sAct + (kc & 1) * 4096;
        const float* wk  = sW + kc * 32 * 8 + ch * 4;
#pragma unroll
        for (int k = 0; k < 32; k++) {
            float a = buf[k * 128 + r];
            u64 aa  = pack2(a, a);
            ulonglong2 w = *(const ulonglong2*)(wk + k * 8);
            fma2(acc0, aa, w.x);
            fma2(acc1, aa, w.y);
        }
        __syncthreads();
    }
    float2 u0 = unpack2(acc0), u1 = unpack2(acc1);
    __stcg(gout_cm + (ch * 4 + 0) * 128 + r, fmaxf(u0.x, 0.f));
    __stcg(gout_cm + (ch * 4 + 1) * 128 + r, fmaxf(u0.y, 0.f));
    __stcg(gout_cm + (ch * 4 + 2) * 128 + r, fmaxf(u1.x, 0.f));
    __stcg(gout_cm + (ch * 4 + 3) * 128 + r, fmaxf(u1.y, 0.f));
}

// ---- stage 2: h2 cols -> bf16 hi/lo mma A-fragments in gmem ----
__device__ __forceinline__ void stage2_frag(const float* __restrict__ gin_cm,
                                            const float* __restrict__ sW,
                                            const float* __restrict__ sb,
                                            u32* __restrict__ fHi,
                                            u32* __restrict__ fLo,
                                            int g, float* __restrict__ sAct, int tid) {
    const int r  = tid & 127;
    const int ch = tid >> 7;
    u64 acc0 = pack2(sb[ch * 4 + 0], sb[ch * 4 + 1]);
    u64 acc1 = pack2(sb[ch * 4 + 2], sb[ch * 4 + 3]);

    const float4* src = (const float4*)gin_cm;
    float4 v0 = __ldcg(src + 0 * 256 + tid);
    float4 v1 = __ldcg(src + 1 * 256 + tid);
    float4 v2 = __ldcg(src + 2 * 256 + tid);
    float4 v3 = __ldcg(src + 3 * 256 + tid);

#pragma unroll 1
    for (int kc = 0; kc < 8; kc++) {
        float4* buf4 = (float4*)(sAct + (kc & 1) * 4096);
        buf4[0 * 256 + tid] = v0;
        buf4[1 * 256 + tid] = v1;
        buf4[2 * 256 + tid] = v2;
        buf4[3 * 256 + tid] = v3;
        __syncthreads();
        if (kc + 1 < 8) {
            const float4* sn = src + (kc + 1) * 1024;
            v0 = __ldcg(sn + 0 * 256 + tid);
            v1 = __ldcg(sn + 1 * 256 + tid);
            v2 = __ldcg(sn + 2 * 256 + tid);
            v3 = __ldcg(sn + 3 * 256 + tid);
        }
        const float* buf = sAct + (kc & 1) * 4096;
        const float* wk  = sW + kc * 32 * 8 + ch * 4;
#pragma unroll
        for (int k = 0; k < 32; k++) {
            float a = buf[k * 128 + r];
            u64 aa  = pack2(a, a);
            ulonglong2 w = *(const ulonglong2*)(wk + k * 8);
            fma2(acc0, aa, w.x);
            fma2(acc1, aa, w.y);
        }
        __syncthreads();
    }
    float2 u0 = unpack2(acc0), u1 = unpack2(acc1);
    float o0 = fmaxf(u0.x, 0.f), o1 = fmaxf(u0.y, 0.f);
    float o2 = fmaxf(u1.x, 0.f), o3 = fmaxf(u1.y, 0.f);

    unsigned short h0, h1, h2, h3, l0, l1, l2, l3;
    bf_split(o0, h0, l0); bf_split(o1, h1, l1);
    bf_split(o2, h2, l2); bf_split(o3, h3, l3);
    u32 hi01 = ((u32)h1 << 16) | h0;
    u32 hi23 = ((u32)h3 << 16) | h2;
    u32 lo01 = ((u32)l1 << 16) | l0;
    u32 lo23 = ((u32)l3 << 16) | l2;

    // fragment slot: cols c = g*8 + ch*4 + j ; kt = g>>1 ; within-tile k = 8*(g&1)+4ch+j
    const int kt   = g >> 1;
    const int mt   = r >> 4;
    const int lane = (r & 7) * 4 + 2 * ch;
    const int reg  = ((r >> 3) & 1) + 2 * (g & 1);
    const int idx0 = ((kt * 8 + mt) * 32 + lane) * 4 + reg;
    __stcg(&fHi[idx0], hi01);
    __stcg(&fHi[idx0 + 4], hi23);
    __stcg(&fLo[idx0], lo01);
    __stcg(&fLo[idx0 + 4], lo23);
}

// ================= persistent kernel =================
__global__ void __launch_bounds__(TPB, 1)
cde_persistent(const float* __restrict__ t, const float* __restrict__ z0,
               const float* __restrict__ X,
               const float* __restrict__ W1, const float* __restrict__ b1,
               const float* __restrict__ W2, const float* __restrict__ b2,
               const float* __restrict__ W3, const float* __restrict__ b3,
               const float* __restrict__ mW, const float* __restrict__ mb,
               const float* __restrict__ sWp, const float* __restrict__ sbp,
               float* __restrict__ out) {
    extern __shared__ char smb[];
    uint4* sFragB = (uint4*)(smb + SM_FRAGB);
    float* sW1  = (float*)(smb + SM_W1);
    float* sW2  = (float*)(smb + SM_W2);
    float* sb3  = (float*)(smb + SM_B3);
    float* sb1  = (float*)(smb + SM_B1);
    float* sb2  = (float*)(smb + SM_B2);
    float* smW  = (float*)(smb + SM_MW);
    float* ssW  = (float*)(smb + SM_SW);
    float* smb_ = (float*)(smb + SM_MB);
    float* ssb  = (float*)(smb + SM_SB);
    float* sDx  = (float*)(smb + SM_DX);
    float* sAct = (float*)(smb + SM_ACT);
    float* sKb  = (float*)(smb + SM_KB);

    const int tid  = threadIdx.x;
    const int wid  = tid >> 5;
    const int lane = tid & 31;
    const int bb   = blockIdx.x >> 5;
    const int g    = blockIdx.x & 31;
    const int rowBase = bb * 128;

    // ---- init: W3 slice -> B fragments (hi/lo) in smem ----
    for (int i = tid; i < 16 * 16 * 32; i += TPB) {
        int ln = i & 31, nt = (i >> 5) & 15, kt = i >> 9;
        int nl = nt * 8 + (ln >> 2);
        int k0 = kt * 16 + (ln & 3) * 2;
        const float* wp = W3 + (size_t)k0 * 4096 + g * 128 + nl;
        unsigned short h0, h1, h8, h9, l0, l1, l8, l9;
        bf_split(wp[0],          h0, l0);
        bf_split(wp[4096],       h1, l1);
        bf_split(wp[8 * 4096],   h8, l8);
        bf_split(wp[9 * 4096],   h9, l9);
        uint4 v;
        v.x = ((u32)h1 << 16) | h0;   // bhi0: k0, k0+1
        v.y = ((u32)h9 << 16) | h8;   // bhi1: k0+8, k0+9
        v.z = ((u32)l1 << 16) | l0;   // blo0
        v.w = ((u32)l9 << 16) | l8;   // blo1
        sFragB[i] = v;
    }
    for (int i = tid; i < 128 * 2; i += TPB) {
        int k = i >> 1, c4 = i & 1;
        *(float4*)(sW1 + k * 8 + c4 * 4) =
            __ldg((const float4*)(W1 + (size_t)k * 256 + g * 8) + c4);
    }
    for (int i = tid; i < 256 * 2; i += TPB) {
        int k = i >> 1, c4 = i & 1;
        *(float4*)(sW2 + k * 8 + c4 * 4) =
            __ldg((const float4*)(W2 + (size_t)k * 256 + g * 8) + c4);
    }
    for (int i = tid; i < 128; i += TPB) sb3[i] = __ldg(&b3[g * 128 + i]);
    if (tid < 8)  sb1[tid] = __ldg(&b1[g * 8 + tid]);
    if (tid >= 8 && tid < 16) sb2[tid - 8] = __ldg(&b2[g * 8 + tid - 8]);
    for (int i = tid; i < 256; i += TPB) {
        int h = i >> 1, c = i & 1;
        smW[i] = __ldg(&mW[(size_t)h * 64 + g * 2 + c]);
        ssW[i] = __ldg(&sWp[(size_t)h * 64 + g * 2 + c]);
    }
    if (tid < 2)  smb_[tid] = __ldg(&mb[g * 2 + tid]);
    if (tid >= 2 && tid < 4) ssb[tid - 2] = __ldg(&sbp[g * 2 + tid - 2]);
    __syncthreads();

    // ---- RK state: thread tid<128 owns z[rowBase+tid, g*4 .. +3] ----
    float zb[4];
    if (tid < 128) {
#pragma unroll
        for (int h = 0; h < 4; h++)
            zb[h] = __ldg(&z0[(size_t)(rowBase + tid) * 128 + g * 4 + h]);
    }

    const size_t zOff  = (size_t)bb * (NH * 128);
    const size_t h1Off = (size_t)bb * (NBN * 128);

    unsigned ph = 0;                // parity driver (same scheme as R5)
    unsigned cz = 0, c1 = 0, c2 = 0; // per-type arrive phases
    const int r0 = wid * 16 + (lane >> 2);
    const int t4 = lane & 3;

#pragma unroll 1
    for (int tau = 0; tau < NIVL; tau++) {
        float t0v = __ldg(&t[tau]);
        float t1v = __ldg(&t[tau + 1]);
        float dti = t1v - t0v;
        float hstep = dti * 0.25f;
        __syncthreads();
        for (int i = tid; i < 1024; i += TPB) {
            int rr = i >> 3, q = i & 7;
            const float* Xr = X + ((size_t)(rowBase + rr) * NTT + tau) * NIN;
            float4 x0 = __ldg((const float4*)Xr + q);
            float4 x1 = __ldg((const float4*)(Xr + NIN) + q);
            float* d = sDx + rr * 33 + q * 4;
            d[0] = (x1.x - x0.x) / dti;
            d[1] = (x1.y - x0.y) / dti;
            d[2] = (x1.z - x0.z) / dti;
            d[3] = (x1.w - x0.w) / dti;
        }
        __syncthreads();

        // hoist this thread's dxdt values for the interval
        float dx0[8], dx1[8];
#pragma unroll
        for (int q = 0; q < 8; q++) {
            int i = (q >> 1) * 8 + t4 * 2 + (q & 1);
            dx0[q] = sDx[r0 * 33 + i];
            dx1[q] = sDx[(r0 + 8) * 33 + i];
        }

#pragma unroll 1
        for (int sub = 0; sub < 4; sub++) {
            float a_acc[4] = {0.f, 0.f, 0.f, 0.f};
            float kp[4]    = {0.f, 0.f, 0.f, 0.f};
#pragma unroll 1
            for (int s = 0; s < 4; s++) {
                float cs = (s == 0) ? 0.f : ((s == 3) ? 1.f : 0.5f);

                // publish zc (col-major)
                ++ph; int pz = ph & 1;
                if (tid < 128) {
#pragma unroll
                    for (int h = 0; h < 4; h++) {
                        float zc = fmaf(cs * hstep, kp[h], zb[h]);
                        __stcg(&g_zc[pz][zOff + (size_t)(g * 4 + h) * 128 + tid], zc);
                    }
                }
                publish_cnt(&g_cz[bb]);
                ++cz;
                wait_cnt(&g_cz[bb], cz * 32);

                // stage 1
                ++ph; int p1 = ph & 1;
                stage1(&g_zc[pz][zOff], sW1, sb1,
                       &g_h1[p1][h1Off + (size_t)(g * 8) * 128], sAct, tid);
                publish_cnt(&g_c1[bb]);
                ++c1;
                wait_cnt(&g_c1[bb], c1 * 32);

                // stage 2 -> A fragments
                ++ph; int p2 = ph & 1;
                stage2_frag(&g_h1[p1][h1Off], sW2, sb2,
                            (u32*)&g_fAhi[p2][bb][0], (u32*)&g_fAlo[p2][bb][0],
                            g, sAct, tid);
                publish_cnt(&g_c2[bb]);
                ++c2;
                wait_cnt(&g_c2[bb], c2 * 32);

                // ---- stage 3: mma.sync over fragments ----
                float acc[16][4];
                {
                    const int c0b = t4 * 2;
#pragma unroll
                    for (int nt = 0; nt < 16; nt++) {
                        float bx = sb3[nt * 8 + c0b];
                        float by = sb3[nt * 8 + c0b + 1];
                        acc[nt][0] = bx; acc[nt][1] = by;
                        acc[nt][2] = bx; acc[nt][3] = by;
                    }
                }
                const uint4* fAh = &g_fAhi[p2][bb][0];
                const uint4* fAl = &g_fAlo[p2][bb][0];
                uint4 ah = __ldcg(fAh + (0 * 8 + wid) * 32 + lane);
                uint4 al = __ldcg(fAl + (0 * 8 + wid) * 32 + lane);
#pragma unroll 1
                for (int kt = 0; kt < 16; kt++) {
                    uint4 ahn, aln;
                    if (kt < 15) {
                        ahn = __ldcg(fAh + ((kt + 1) * 8 + wid) * 32 + lane);
                        aln = __ldcg(fAl + ((kt + 1) * 8 + wid) * 32 + lane);
                    }
                    const uint4* bfr = sFragB + (kt * 16) * 32 + lane;
#pragma unroll
                    for (int nt = 0; nt < 16; nt++) {
                        uint4 b = bfr[nt * 32];
                        mma16816(acc[nt], ah, b.x, b.y);   // Ahi*Bhi
                        mma16816(acc[nt], ah, b.z, b.w);   // Ahi*Blo
                        mma16816(acc[nt], al, b.x, b.y);   // Alo*Bhi
                    }
                    ah = ahn; al = aln;
                }

                // epilogue: tanh + dxdt contraction (bias pre-seeded)
                float kq0[4] = {0.f, 0.f, 0.f, 0.f};
                float kq1[4] = {0.f, 0.f, 0.f, 0.f};
#pragma unroll
                for (int nt = 0; nt < 16; nt++) {
                    int hl = nt >> 2, q = (nt & 3) * 2;
                    float y;
                    y = fast_tanh(acc[nt][0]); kq0[hl] = fmaf(y, dx0[q],     kq0[hl]);
                    y = fast_tanh(acc[nt][1]); kq0[hl] = fmaf(y, dx0[q + 1], kq0[hl]);
                    y = fast_tanh(acc[nt][2]); kq1[hl] = fmaf(y, dx1[q],     kq1[hl]);
                    y = fast_tanh(acc[nt][3]); kq1[hl] = fmaf(y, dx1[q + 1], kq1[hl]);
                }
#pragma unroll
                for (int hl = 0; hl < 4; hl++) {
                    sKb[r0 * 17 + hl * 4 + t4]       = kq0[hl];
                    sKb[(r0 + 8) * 17 + hl * 4 + t4] = kq1[hl];
                }
                __syncthreads();

                if (tid < 128) {
                    float ws = (s == 0 || s == 3) ? 1.f : 2.f;
                    const float* kb = sKb + tid * 17;
#pragma unroll
                    for (int h = 0; h < 4; h++) {
                        float kv = (kb[h * 4] + kb[h * 4 + 1])
                                 + (kb[h * 4 + 2] + kb[h * 4 + 3]);
                        a_acc[h] = fmaf(ws, kv, a_acc[h]);
                        kp[h] = kv;
                    }
                }
                __syncthreads();
            }
            if (tid < 128) {
                float h6 = hstep / 6.0f;
#pragma unroll
                for (int h = 0; h < 4; h++) zb[h] = fmaf(h6, a_acc[h], zb[h]);
            }
        }

        // ---- interval end: publish final z, output heads ----
        ++ph; int pz = ph & 1;
        if (tid < 128) {
#pragma unroll
            for (int h = 0; h < 4; h++)
                __stcg(&g_zc[pz][zOff + (size_t)(g * 4 + h) * 128 + tid], zb[h]);
        }
        publish_cnt(&g_cz[bb]);
        ++cz;
        wait_cnt(&g_cz[bb], cz * 32);
        {
            const int r  = tid & 127;
            const int hh = tid >> 7;
            const int b  = rowBase + r;
            const float* wsel = hh ? ssW : smW;
            float acc0 = hh ? ssb[0] : smb_[0];
            float acc1 = hh ? ssb[1] : smb_[1];
            const float* zbase = &g_zc[pz][zOff];
#pragma unroll 8
            for (int h = 0; h < 128; h++) {
                float zv = __ldcg(zbase + (size_t)h * 128 + r);
                acc0 = fmaf(zv, wsel[h * 2 + 0], acc0);
                acc1 = fmaf(zv, wsel[h * 2 + 1], acc1);
            }
            if (hh) { acc0 = softplus_f(acc0); acc1 = softplus_f(acc1); }
            float* dst = out + (hh ? (size_t)NBATCH * NIVL * NOUT : 0)
                         + ((size_t)b * NIVL + tau) * NOUT + g * 2;
            dst[0] = acc0;
            dst[1] = acc1;
        }
    }

    // ---- end-of-kernel reset for deterministic graph replay ----
    gbar_val(bb, 1u);                 // all CTAs of group done polling counters
    if (tid == 0 && g == 0) {
        g_cz[bb].v = 0u;
        g_c1[bb].v = 0u;
        g_c2[bb].v = 0u;
    }
    gbar_val(bb, 0u);                 // restores g_rel to 0 (g_cnt self-resets)
}

extern "C" void kernel_launch(void* const* d_in, const int* in_sizes, int n_in,
                              void* d_out, int out_size) {
    const float* t   = (const float*)d_in[0];
    const float* z0  = (const float*)d_in[1];
    const float* X   = (const float*)d_in[2];
    const float* W1  = (const float*)d_in[3];
    const float* b1  = (const float*)d_in[4];
    const float* W2  = (const float*)d_in[5];
    const float* b2  = (const float*)d_in[6];
    const float* W3  = (const float*)d_in[7];
    const float* b3  = (const float*)d_in[8];
    const float* mW  = (const float*)d_in[9];
    const float* mb  = (const float*)d_in[10];
    const float* sW  = (const float*)d_in[11];
    const float* sb  = (const float*)d_in[12];
    float* out = (float*)d_out;

    cudaFuncSetAttribute(cde_persistent,
                         cudaFuncAttributeMaxDynamicSharedMemorySize, SMEM_BYTES);
    cde_persistent<<<GRID_CTAS, TPB, SMEM_BYTES>>>(t, z0, X, W1, b1, W2, b2,
                                                   W3, b3, mW, mb, sW, sb, out);
}